// round 2
// baseline (speedup 1.0000x reference)
#include <cuda_runtime.h>

#define BB      8
#define NN      4096
#define CC      64      // feature dim
#define KD      32      // top-k kept before dilation
#define KOUT    16      // neighbors output
#define QT      128     // queries per CTA
#define CT      64      // candidates per chunk
#define NTHREADS 256

// smem layout (floats):
//   qT   [64][128]  k-major query tile          8192 f
//   cT   [64][64]   k-major candidate tile      4096 f  (f4-swizzled)
//   dist [64][128]  inner products, c-major     8192 f  (f2-swizzled)
//   sqc  [64]                                     64 f
//   topk [128][32]  u64 keys                   32768 B
#define SMEM_FLOATS (8192 + 4096 + 8192 + 64)
#define SMEM_BYTES  (SMEM_FLOATS * 4 + QT * KD * 8)   // 114944

__device__ __forceinline__ void fma2(unsigned long long& d,
                                     unsigned long long a,
                                     unsigned long long b) {
    asm("fma.rn.f32x2 %0, %1, %2, %0;" : "+l"(d) : "l"(a), "l"(b));
}
__device__ __forceinline__ unsigned long long pack2(float x) {
    unsigned long long r;
    asm("mov.b64 %0, {%1, %1};" : "=l"(r) : "f"(x));
    return r;
}
// order-preserving float->uint map (handles negatives like a signed compare)
__device__ __forceinline__ unsigned int ord32(float f) {
    unsigned int b = __float_as_uint(f);
    return b ^ ((b & 0x80000000u) ? 0xFFFFFFFFu : 0x80000000u);
}

__global__ void __launch_bounds__(NTHREADS, 2)
knn_pe_kernel(const float* __restrict__ xyz,   // [B,N,3]
              const float* __restrict__ pts,   // [B,N,64]
              float* __restrict__ out)         // [B,N,16,10]
{
    extern __shared__ float smem[];
    float* qT   = smem;                  // 64*128
    float* cT   = qT + 64 * QT;          // 64*64
    float* dist = cT + 64 * CT;          // 64*128
    float* sqc  = dist + 64 * QT;        // 64
    unsigned long long* topk = (unsigned long long*)(sqc + 64); // 128*32

    const int tid   = threadIdx.x;
    const int b     = blockIdx.y;
    const int qbase = blockIdx.x * QT;
    const float* ptsB = pts + (size_t)b * NN * CC;

    // ---- load query tile transposed (k-major). 2048 float4 reads, coalesced.
    {
        const float4* g = (const float4*)(ptsB + (size_t)qbase * CC);
        for (int f = tid; f < QT * (CC / 4); f += NTHREADS) {
            int row = f >> 4;            // query 0..127
            int k4  = (f & 15) << 2;     // feature base
            float4 v = g[f];
            qT[(k4 + 0) * QT + row] = v.x;
            qT[(k4 + 1) * QT + row] = v.y;
            qT[(k4 + 2) * QT + row] = v.z;
            qT[(k4 + 3) * QT + row] = v.w;
        }
    }
    for (int i = tid; i < QT * KD; i += NTHREADS)
        topk[i] = 0xFFFFFFFFFFFFFFFFull;
    __syncthreads();

    // ---- per-query squared norm, XLA-style: rounded products, x2-vectorized
    //      warp tree: a_l = x[2l]^2 + x[2l+1]^2, then butterfly 16,8,4,2,1.
    float sqQ = 0.0f;
    if (tid < QT) {
        float a[32];
        #pragma unroll
        for (int l = 0; l < 32; ++l) {
            float x0 = qT[(2 * l) * QT + tid];
            float x1 = qT[(2 * l + 1) * QT + tid];
            a[l] = __fadd_rn(__fmul_rn(x0, x0), __fmul_rn(x1, x1));
        }
        #pragma unroll
        for (int off = 16; off >= 1; off >>= 1)
            #pragma unroll
            for (int l = 0; l < 16; ++l)
                if (l < off) a[l] = __fadd_rn(a[l], a[l + off]);
        sqQ = a[0];
    }

    const int qg = tid >> 4;   // 0..15 : query group (8 queries)
    const int cg = tid & 15;   // 0..15 : candidate group (4 candidates)
    unsigned long long thresh = 0xFFFFFFFFFFFFFFFFull;

    for (int chunk = 0; chunk < NN / CT; ++chunk) {
        const int cbase = chunk * CT;

        // prefetch candidate tile from global (coalesced), 4 float4 / thread
        float4 pf[4];
        {
            const float4* g = (const float4*)(ptsB + (size_t)cbase * CC);
            #pragma unroll
            for (int it = 0; it < 4; ++it)
                pf[it] = g[it * NTHREADS + tid];
        }
        __syncthreads();   // prev chunk: GEMM done with cT, selection done with dist

        // store transposed + swizzled: phys_f4_col = (c>>2) ^ (k>>2)
        #pragma unroll
        for (int it = 0; it < 4; ++it) {
            int f    = it * NTHREADS + tid;
            int c    = f >> 4;
            int k4g  = f & 15;                 // = k>>2
            int phys = (c >> 2) ^ k4g;
            int base = (k4g << 2) * CT + (phys << 2) + (c & 3);
            cT[base + 0 * CT] = pf[it].x;
            cT[base + 1 * CT] = pf[it].y;
            cT[base + 2 * CT] = pf[it].z;
            cT[base + 3 * CT] = pf[it].w;
        }
        __syncthreads();

        // per-candidate squared norm, same XLA-style tree
        if (tid < CT) {
            float a[32];
            #pragma unroll
            for (int l = 0; l < 32; ++l) {
                int k0 = 2 * l, k1 = 2 * l + 1;
                float x0 = cT[k0 * CT + ((((tid >> 2) ^ ((k0 >> 2) & 15)) << 2) | (tid & 3))];
                float x1 = cT[k1 * CT + ((((tid >> 2) ^ ((k1 >> 2) & 15)) << 2) | (tid & 3))];
                a[l] = __fadd_rn(__fmul_rn(x0, x0), __fmul_rn(x1, x1));
            }
            #pragma unroll
            for (int off = 16; off >= 1; off >>= 1)
                #pragma unroll
                for (int l = 0; l < 16; ++l)
                    if (l < off) a[l] = __fadd_rn(a[l], a[l + off]);
            sqc[tid] = a[0];
        }

        // ---- GEMM: inner[q][c] for 8 queries x 4 candidates per thread,
        //      f32x2 packs query pairs. (matches cuBLAS: ascending-k fma chain)
        unsigned long long acc[4][4];
        #pragma unroll
        for (int i = 0; i < 4; ++i)
            #pragma unroll
            for (int j = 0; j < 4; ++j) acc[i][j] = 0ull;

        #pragma unroll 8
        for (int k = 0; k < CC; ++k) {
            const float* qrow = qT + k * QT + (qg << 3);
            ulonglong2 aa = *(const ulonglong2*)(qrow);      // (q0,q1),(q2,q3)
            ulonglong2 ab = *(const ulonglong2*)(qrow + 4);  // (q4,q5),(q6,q7)
            int phys = cg ^ ((k >> 2) & 15);
            float4 bv = *(const float4*)(cT + k * CT + (phys << 2));
            unsigned long long b0 = pack2(bv.x);
            unsigned long long b1 = pack2(bv.y);
            unsigned long long b2 = pack2(bv.z);
            unsigned long long b3 = pack2(bv.w);
            fma2(acc[0][0], aa.x, b0); fma2(acc[0][1], aa.x, b1);
            fma2(acc[0][2], aa.x, b2); fma2(acc[0][3], aa.x, b3);
            fma2(acc[1][0], aa.y, b0); fma2(acc[1][1], aa.y, b1);
            fma2(acc[1][2], aa.y, b2); fma2(acc[1][3], aa.y, b3);
            fma2(acc[2][0], ab.x, b0); fma2(acc[2][1], ab.x, b1);
            fma2(acc[2][2], ab.x, b2); fma2(acc[2][3], ab.x, b3);
            fma2(acc[3][0], ab.y, b0); fma2(acc[3][1], ab.y, b1);
            fma2(acc[3][2], ab.y, b2); fma2(acc[3][3], ab.y, b3);
        }

        // store inner products c-major, f2-swizzled: phys_f2 = (q>>1) ^ (c>>2)
        #pragma unroll
        for (int j = 0; j < 4; ++j) {
            int c = (cg << 2) + j;
            #pragma unroll
            for (int i = 0; i < 4; ++i) {
                int f2   = (qg << 2) + i;        // q0>>1
                int phys = f2 ^ cg;              // cg == c>>2
                *(unsigned long long*)(dist + c * QT + (phys << 1)) = acc[i][j];
            }
        }
        __syncthreads();

        // ---- selection: thread q scans the 64 new distances
        if (tid < QT) {
            unsigned long long* row = topk + tid * KD;
            for (int c = 0; c < CT; ++c) {
                int phys = (tid >> 1) ^ (c >> 2);
                float inner = dist[c * QT + (phys << 1) + (tid & 1)];
                // (sq_n - 2*inner) + sq_m ; fma is exact-equivalent since 2*inner exact
                float adj = __fadd_rn(fmaf(-2.0f, inner, sqQ), sqc[c]);
                unsigned long long key =
                    ((unsigned long long)ord32(adj) << 32) |
                    (unsigned int)(cbase + c);
                if (key < thresh) {
                    int p = KD - 1;
                    while (p > 0 && row[p - 1] > key) { row[p] = row[p - 1]; --p; }
                    row[p] = key;
                    thresh = row[KD - 1];
                }
            }
        }
    }

    // ---- epilogue: gather xyz for even ranks (dilation 2), write [dis,rel,xyz,nb]
    if (tid < QT) {
        int qglob = qbase + tid;
        const float* xb = xyz + ((size_t)b * NN + qglob) * 3;
        float x0 = xb[0], x1 = xb[1], x2 = xb[2];
        float* o = out + (((size_t)b * NN + qglob) * KOUT) * 10;
        const unsigned long long* row = topk + tid * KD;
        #pragma unroll 4
        for (int j = 0; j < KOUT; ++j) {
            unsigned int idx = (unsigned int)(row[2 * j] & 0xFFFFFFFFull);
            const float* nb = xyz + ((size_t)b * NN + idx) * 3;
            float n0 = nb[0], n1 = nb[1], n2 = nb[2];
            float r0 = x0 - n0, r1 = x1 - n1, r2 = x2 - n2;
            float d  = sqrtf(r0 * r0 + r1 * r1 + r2 * r2);
            float* oj = o + j * 10;
            oj[0] = d;
            oj[1] = r0; oj[2] = r1; oj[3] = r2;
            oj[4] = x0; oj[5] = x1; oj[6] = x2;
            oj[7] = n0; oj[8] = n1; oj[9] = n2;
        }
    }
}

extern "C" void kernel_launch(void* const* d_in, const int* in_sizes, int n_in,
                              void* d_out, int out_size) {
    const float* in0 = (const float*)d_in[0];
    const float* in1 = (const float*)d_in[1];
    const float* xyz;
    const float* pts;
    if (in_sizes[0] == BB * NN * 3) { xyz = in0; pts = in1; }
    else                            { xyz = in1; pts = in0; }

    cudaFuncSetAttribute(knn_pe_kernel,
                         cudaFuncAttributeMaxDynamicSharedMemorySize, SMEM_BYTES);

    dim3 grid(NN / QT, BB);
    knn_pe_kernel<<<grid, NTHREADS, SMEM_BYTES>>>(xyz, pts, (float*)d_out);
}